// round 17
// baseline (speedup 1.0000x reference)
#include <cuda_runtime.h>
#include <cuda_bf16.h>
#include <cstdint>

#define EMB    256
#define K1     512
#define PAIRS  15
#define M_TOT  16384
#define KF     3840            // PAIRS*EMB

__constant__ int c_i[PAIRS] = {0,0,0,0,0,1,1,1,1,2,2,2,3,3,4};
__constant__ int c_j[PAIRS] = {1,2,3,4,5,2,3,4,5,3,4,5,4,5,5};

// Scratch (device globals: allocation-guard safe)
__device__ __nv_bfloat16 g_Wphi[(size_t)PAIRS * EMB * K1];   // W_pair^T hi  [p][n][k]
__device__ __nv_bfloat16 g_Wplo[(size_t)PAIRS * EMB * K1];   // W_pair^T lo
__device__ __nv_bfloat16 g_Wfhi[(size_t)EMB * KF];           // W_final^T hi [n][k]
__device__ __nv_bfloat16 g_Wflo[(size_t)EMB * KF];           // W_final^T lo
__device__ __nv_bfloat16 g_Hhi[(size_t)PAIRS * M_TOT * EMB]; // h hi [p][m][d]
__device__ __nv_bfloat16 g_Hlo[(size_t)PAIRS * M_TOT * EMB]; // h lo

__device__ __forceinline__ bool pair_active(const int* __restrict__ NAS, int p) {
    const int i = c_i[p], j = c_j[p];
    const int ni = (i < 2) ? 1 : NAS[i];
    const int nj = (j < 2) ? 1 : NAS[j];
    return (ni != 0) && (nj != 0);
}

__device__ __forceinline__ float tanh_fast(float x) {
    float y; asm("tanh.approx.f32 %0, %1;" : "=f"(y) : "f"(x)); return y;
}
__device__ __forceinline__ uint32_t s2u(const void* p) {
    uint32_t a;
    asm("{ .reg .u64 t; cvta.to.shared.u64 t, %1; cvt.u32.u64 %0, t; }" : "=r"(a) : "l"(p));
    return a;
}
// pack (x,y) -> bf16x2 with x in low half (memory order [x,y])
__device__ __forceinline__ uint32_t packbf(float x, float y) {
    uint32_t r; asm("cvt.rn.bf16x2.f32 %0, %1, %2;" : "=r"(r) : "f"(y), "f"(x));
    return r;
}
// residual pair: lo = val - float(hi)
__device__ __forceinline__ uint32_t lopair(uint32_t hp, float x, float y) {
    float hx = __uint_as_float(hp << 16);
    float hy = __uint_as_float(hp & 0xffff0000u);
    return packbf(x - hx, y - hy);
}
__device__ __forceinline__ void ldsm4(uint32_t* r, uint32_t addr) {
    asm volatile("ldmatrix.sync.aligned.m8n8.x4.shared.b16 {%0,%1,%2,%3}, [%4];"
                 : "=r"(r[0]), "=r"(r[1]), "=r"(r[2]), "=r"(r[3]) : "r"(addr));
}
__device__ __forceinline__ void mma16816(float* d, const uint32_t* a, uint32_t b0, uint32_t b1) {
    asm volatile("mma.sync.aligned.m16n8k16.row.col.f32.bf16.bf16.f32 "
                 "{%0,%1,%2,%3}, {%4,%5,%6,%7}, {%8,%9}, {%0,%1,%2,%3};"
                 : "+f"(d[0]), "+f"(d[1]), "+f"(d[2]), "+f"(d[3])
                 : "r"(a[0]), "r"(a[1]), "r"(a[2]), "r"(a[3]), "r"(b0), "r"(b1));
}
__device__ __forceinline__ void cpa16(uint32_t dst, const void* src) {
    asm volatile("cp.async.cg.shared.global [%0], [%1], 16;" :: "r"(dst), "l"(src));
}
#define CP_COMMIT() asm volatile("cp.async.commit_group;" ::: "memory")
#define CP_WAIT1()  asm volatile("cp.async.wait_group 1;" ::: "memory")
#define CP_WAIT0()  asm volatile("cp.async.wait_group 0;" ::: "memory")

// BK=32 stage: A(128x32) hi/lo = 8KB each, B(128x32) hi/lo = 8KB each -> 32KB
#define ST_A_HI 0
#define ST_A_LO 8192
#define ST_B_HI 16384
#define ST_B_LO 24576
#define STAGE   32768
#define NSTAGES 3
#define SM_STG  1024
#define SMEM_BYTES (SM_STG + NSTAGES * STAGE)   // 99328 -> 2 CTAs/SM

// 64B logical rows (32 bf16), two rows packed per 128B line, XOR-swizzled chunks.
__device__ __forceinline__ uint32_t swoff32(int row, int u) {
    int line  = row >> 1;
    int inner = (((row & 1) << 2) | u) ^ (line & 7);
    return (uint32_t)(line * 128 + inner * 16);
}

// ---- one (A-array, B-array) sweep over the BK=32 stage -----------------
// 8 warps (4m x 2n), warp tile 32(m) x 64(n). All 16 mma per kk hit distinct
// accumulators -> no RAW chains (the R16 bottleneck).
__device__ __forceinline__ void sweep(uint32_t a_base, uint32_t b_base,
                                      int warp_m, int warp_n, int lane,
                                      float acc[2][8][4]) {
    const int l15 = lane & 15, lh = lane >> 4;
    #pragma unroll
    for (int kk = 0; kk < 2; kk++) {
        const int ch = kk * 2 + lh;   // 0..3
        uint32_t a[2][4];
        #pragma unroll
        for (int mi = 0; mi < 2; mi++)
            ldsm4(a[mi], a_base + swoff32(warp_m * 32 + mi * 16 + l15, ch));
        #pragma unroll
        for (int ng = 0; ng < 4; ng++) {
            uint32_t b[4];
            ldsm4(b, b_base + swoff32(warp_n * 64 + ng * 16 + l15, ch));
            #pragma unroll
            for (int mi = 0; mi < 2; mi++) {
                mma16816(acc[mi][ng * 2 + 0], a[mi], b[0], b[2]);
                mma16816(acc[mi][ng * 2 + 1], a[mi], b[1], b[3]);
            }
        }
    }
}
__device__ __forceinline__ void stage_mma(uint32_t stb, int warp_m, int warp_n,
                                          int lane, float acc[2][8][4]) {
    sweep(stb + ST_A_HI, stb + ST_B_HI, warp_m, warp_n, lane, acc);  // hi*hi
    sweep(stb + ST_A_HI, stb + ST_B_LO, warp_m, warp_n, lane, acc);  // hi*lo
    sweep(stb + ST_A_LO, stb + ST_B_HI, warp_m, warp_n, lane, acc);  // lo*hi
}

// ---------------------------------------------------------------------------
// Prep: transpose + bf16-split weights
// ---------------------------------------------------------------------------
__global__ void prep_wp(const float* __restrict__ Wp, const int* __restrict__ NAS) {
    const int p = blockIdx.z;
    if (!pair_active(NAS, p)) return;
    __shared__ float t[64][65];
    const int k0 = blockIdx.x * 64, n0 = blockIdx.y * 64;
    const int tid = threadIdx.x;
    #pragma unroll
    for (int i = 0; i < 16; i++) {
        int idx = i * 256 + tid; int r = idx >> 6, c = idx & 63;
        t[r][c] = Wp[((size_t)p * K1 + k0 + r) * EMB + n0 + c];
    }
    __syncthreads();
    #pragma unroll
    for (int i = 0; i < 16; i++) {
        int idx = i * 256 + tid; int r = idx >> 6, c = idx & 63;
        float x = t[c][r];
        __nv_bfloat16 h = __float2bfloat16(x);
        size_t o = ((size_t)p * EMB + n0 + r) * K1 + k0 + c;
        g_Wphi[o] = h;
        g_Wplo[o] = __float2bfloat16(x - __bfloat162float(h));
    }
}
__global__ void prep_wf(const float* __restrict__ Wf, const int* __restrict__ NAS) {
    const int k0 = blockIdx.x * 64;
    if (!pair_active(NAS, k0 >> 8)) return;
    __shared__ float t[64][65];
    const int n0 = blockIdx.y * 64;
    const int tid = threadIdx.x;
    #pragma unroll
    for (int i = 0; i < 16; i++) {
        int idx = i * 256 + tid; int r = idx >> 6, c = idx & 63;
        t[r][c] = Wf[(size_t)(k0 + r) * EMB + n0 + c];
    }
    __syncthreads();
    #pragma unroll
    for (int i = 0; i < 16; i++) {
        int idx = i * 256 + tid; int r = idx >> 6, c = idx & 63;
        float x = t[c][r];
        __nv_bfloat16 h = __float2bfloat16(x);
        size_t o = (size_t)(n0 + r) * KF + k0 + c;
        g_Wfhi[o] = h;
        g_Wflo[o] = __float2bfloat16(x - __bfloat162float(h));
    }
}

// ---------------------------------------------------------------------------
// GEMM1: h[p] = tanh([f_i|f_j] @ W_p + b_p)   (HMMA, split-bf16 3-sweep)
// grid: (128 Mtiles * 2 Ntiles, PAIRS), 256 threads, 2 CTAs/SM, 3-stage pipe
// ---------------------------------------------------------------------------
__global__ __launch_bounds__(256, 2)
void k_pair_mma(const float* __restrict__ feat, const float* __restrict__ bp,
                const int* __restrict__ NAS)
{
    extern __shared__ char smem[];
    const int p = blockIdx.y;
    if (!pair_active(NAS, p)) return;
    const int tid = threadIdx.x, lane = tid & 31, wid = tid >> 5;
    const int warp_m = wid & 3, warp_n = wid >> 2;
    const int bm = (blockIdx.x >> 1) * 128, bn = (blockIdx.x & 1) * 128;
    const uint32_t sb = s2u(smem);
    float* bias_s = (float*)smem;
    if (tid < 32) ((float4*)bias_s)[tid] = ((const float4*)(bp + p * EMB + bn))[tid];

    const __nv_bfloat16* WH = g_Wphi + ((size_t)p * EMB + bn) * K1;
    const __nv_bfloat16* WL = g_Wplo + ((size_t)p * EMB + bn) * K1;

    float acc[2][8][4];
    #pragma unroll
    for (int a = 0; a < 2; a++)
        #pragma unroll
        for (int b = 0; b < 8; b++)
            #pragma unroll
            for (int c = 0; c < 4; c++) acc[a][b][c] = 0.f;

    const int NT = K1 / 32;   // 16
    float4 av[2][2];          // A regs for stage t+1 (stsA'd at iter t)

    auto issueB = [&](int t) {
        const int buf = t % NSTAGES;
        const int k0 = t * 32;
        #pragma unroll
        for (int it = 0; it < 2; it++) {
            int c = it * 256 + tid; int row = c >> 2, u = c & 3;
            uint32_t d = sb + SM_STG + buf * STAGE + swoff32(row, u);
            cpa16(d + ST_B_HI, WH + (size_t)row * K1 + k0 + u * 8);
            cpa16(d + ST_B_LO, WL + (size_t)row * K1 + k0 + u * 8);
        }
    };
    auto ldgA = [&](int t) {
        const int k0 = t * 32;
        const int f  = (k0 < EMB) ? c_i[p] : c_j[p];
        const float* A = feat + ((size_t)f * M_TOT + bm) * EMB + (k0 & (EMB - 1));
        #pragma unroll
        for (int it = 0; it < 2; it++) {
            int c = it * 256 + tid; int row = c >> 2, u = c & 3;
            av[it][0] = *reinterpret_cast<const float4*>(A + (size_t)row * EMB + u * 8);
            av[it][1] = *reinterpret_cast<const float4*>(A + (size_t)row * EMB + u * 8 + 4);
        }
    };
    auto stsA = [&](int t) {
        const int buf = t % NSTAGES;
        #pragma unroll
        for (int it = 0; it < 2; it++) {
            int c = it * 256 + tid; int row = c >> 2, u = c & 3;
            uint4 hq, lq;
            hq.x = packbf(av[it][0].x, av[it][0].y); lq.x = lopair(hq.x, av[it][0].x, av[it][0].y);
            hq.y = packbf(av[it][0].z, av[it][0].w); lq.y = lopair(hq.y, av[it][0].z, av[it][0].w);
            hq.z = packbf(av[it][1].x, av[it][1].y); lq.z = lopair(hq.z, av[it][1].x, av[it][1].y);
            hq.w = packbf(av[it][1].z, av[it][1].w); lq.w = lopair(hq.w, av[it][1].z, av[it][1].w);
            char* base = smem + SM_STG + buf * STAGE + swoff32(row, u);
            *reinterpret_cast<uint4*>(base + ST_A_HI) = hq;
            *reinterpret_cast<uint4*>(base + ST_A_LO) = lq;
        }
    };

    // prologue: A(0) in smem, av=A(1); B(0),B(1) committed as separate groups
    ldgA(0); stsA(0);
    issueB(0); CP_COMMIT();
    ldgA(1);
    issueB(1); CP_COMMIT();

    for (int t = 0; t < NT; t++) {
        CP_WAIT1();          // group t done (t+1 may still fly)
        __syncthreads();     // all warps done with buffer (t-1): safe to refill (t+2)%3
        if (t + 1 < NT) stsA(t + 1);             // av holds A(t+1)
        if (t + 2 < NT) { issueB(t + 2); CP_COMMIT(); ldgA(t + 2); }
        else            { CP_COMMIT(); }          // keep group count consistent
        stage_mma(sb + SM_STG + (t % NSTAGES) * STAGE, warp_m, warp_n, lane, acc);
        __syncthreads();     // stsA(t+1) visible + compute(t) done before next refill
    }

    // epilogue: bias + tanh -> hi/lo bf16 in g_H
    const int r0 = lane >> 2, c2 = (lane & 3) * 2;
    #pragma unroll
    for (int mi = 0; mi < 2; mi++)
        #pragma unroll
        for (int hf = 0; hf < 2; hf++) {
            const int m = bm + warp_m * 32 + mi * 16 + r0 + hf * 8;
            const size_t rb = ((size_t)p * M_TOT + m) * EMB + bn + warp_n * 64;
            #pragma unroll
            for (int ni = 0; ni < 8; ni++) {
                const int col = ni * 8 + c2;
                float x0 = tanh_fast(acc[mi][ni][hf * 2 + 0] + bias_s[warp_n * 64 + col]);
                float x1 = tanh_fast(acc[mi][ni][hf * 2 + 1] + bias_s[warp_n * 64 + col + 1]);
                uint32_t hp = packbf(x0, x1);
                uint32_t lp = lopair(hp, x0, x1);
                *reinterpret_cast<uint32_t*>(g_Hhi + rb + col) = hp;
                *reinterpret_cast<uint32_t*>(g_Hlo + rb + col) = lp;
            }
        }
}

// ---------------------------------------------------------------------------
// GEMM2: out = h_flat @ W_final + b_final (active pairs only)
// grid: 256 CTAs -> single wave at 2 CTAs/SM, 3-stage pipeline
// ---------------------------------------------------------------------------
__global__ __launch_bounds__(256, 2)
void k_final_mma(const float* __restrict__ bf, const int* __restrict__ NAS,
                 float* __restrict__ out)
{
    extern __shared__ char smem[];
    const int tid = threadIdx.x, lane = tid & 31, wid = tid >> 5;
    const int warp_m = wid & 3, warp_n = wid >> 2;
    const int bm = (blockIdx.x >> 1) * 128, bn = (blockIdx.x & 1) * 128;
    const uint32_t sb = s2u(smem);
    float* bias_s = (float*)smem;
    if (tid < 32) ((float4*)bias_s)[tid] = ((const float4*)(bf + bn))[tid];

    int act[PAIRS]; int nact = 0;
    #pragma unroll
    for (int p = 0; p < PAIRS; p++)
        if (pair_active(NAS, p)) act[nact++] = p;
    const int NT = nact * 8;   // 8 k32-stages per active pair

    float acc[2][8][4];
    #pragma unroll
    for (int a = 0; a < 2; a++)
        #pragma unroll
        for (int b = 0; b < 8; b++)
            #pragma unroll
            for (int c = 0; c < 4; c++) acc[a][b][c] = 0.f;

    auto issue = [&](int t) {
        const int buf = t % NSTAGES;
        const int p  = act[t >> 3];
        const int k0 = (t & 7) * 32;
        const __nv_bfloat16* HH = g_Hhi + ((size_t)p * M_TOT + bm) * EMB + k0;
        const __nv_bfloat16* HL = g_Hlo + ((size_t)p * M_TOT + bm) * EMB + k0;
        const __nv_bfloat16* WH = g_Wfhi + (size_t)bn * KF + p * EMB + k0;
        const __nv_bfloat16* WL = g_Wflo + (size_t)bn * KF + p * EMB + k0;
        #pragma unroll
        for (int it = 0; it < 2; it++) {
            int c = it * 256 + tid; int row = c >> 2, u = c & 3;
            uint32_t d = sb + SM_STG + buf * STAGE + swoff32(row, u);
            cpa16(d + ST_A_HI, HH + (size_t)row * EMB + u * 8);
            cpa16(d + ST_A_LO, HL + (size_t)row * EMB + u * 8);
            cpa16(d + ST_B_HI, WH + (size_t)row * KF + u * 8);
            cpa16(d + ST_B_LO, WL + (size_t)row * KF + u * 8);
        }
    };

    issue(0); CP_COMMIT();
    if (NT > 1) { issue(1); CP_COMMIT(); } else { CP_COMMIT(); }

    for (int t = 0; t < NT; t++) {
        CP_WAIT1();
        __syncthreads();
        if (t + 2 < NT) { issue(t + 2); CP_COMMIT(); }
        else            { CP_COMMIT(); }
        stage_mma(sb + SM_STG + (t % NSTAGES) * STAGE, warp_m, warp_n, lane, acc);
        __syncthreads();
    }

    const int r0 = lane >> 2, c2 = (lane & 3) * 2;
    #pragma unroll
    for (int mi = 0; mi < 2; mi++)
        #pragma unroll
        for (int hf = 0; hf < 2; hf++) {
            const int m = bm + warp_m * 32 + mi * 16 + r0 + hf * 8;
            float* ob = out + (size_t)m * EMB + bn + warp_n * 64;
            #pragma unroll
            for (int ni = 0; ni < 8; ni++) {
                const int col = ni * 8 + c2;
                float2 v;
                v.x = acc[mi][ni][hf * 2 + 0] + bias_s[warp_n * 64 + col];
                v.y = acc[mi][ni][hf * 2 + 1] + bias_s[warp_n * 64 + col + 1];
                *reinterpret_cast<float2*>(ob + col) = v;
            }
        }
}

extern "C" void kernel_launch(void* const* d_in, const int* in_sizes, int n_in,
                              void* d_out, int out_size)
{
    const float* feat = (const float*)d_in[0];   // [6, 32, 512, 256]
    const float* Wp   = (const float*)d_in[1];   // [15, 512, 256]
    const float* bp   = (const float*)d_in[2];   // [15, 256]
    const float* Wf   = (const float*)d_in[3];   // [3840, 256]
    const float* bf   = (const float*)d_in[4];   // [256]
    const int*   NAS  = (const int*)d_in[5];     // [6]
    float* out = (float*)d_out;                  // [32, 512, 256]

    cudaFuncSetAttribute(k_pair_mma,  cudaFuncAttributeMaxDynamicSharedMemorySize, SMEM_BYTES);
    cudaFuncSetAttribute(k_final_mma, cudaFuncAttributeMaxDynamicSharedMemorySize, SMEM_BYTES);

    prep_wp<<<dim3(K1 / 64, EMB / 64, PAIRS), 256>>>(Wp, NAS);
    prep_wf<<<dim3(KF / 64, EMB / 64), 256>>>(Wf, NAS);

    k_pair_mma<<<dim3(256, PAIRS), 256, SMEM_BYTES>>>(feat, bp, NAS);
    k_final_mma<<<256, 256, SMEM_BYTES>>>(bf, NAS, out);
}